// round 16
// baseline (speedup 1.0000x reference)
#include <cuda_runtime.h>
#include <cuda_bf16.h>
#include <math.h>

// ---------------------------------------------------------------------------
// HyperGraphEncoder — split-bf16 mma.sync, pre-split operands, cp.async GEMMs,
// GRU recurrence: single kernel/step with intra-grid flag-gated gate epilogue.
// ---------------------------------------------------------------------------

namespace {
constexpr int NB   = 256;
constexpr int HD   = 256;
constexpr int NHEAD = 4;
constexpr int DKH  = 64;
constexpr int TNA  = 127;
constexpr int TNP  = 23;
constexpr int TNH  = 11;
constexpr int G3   = 768;
constexpr int BKP  = 40;             // padded bf16 k-stride in smem
constexpr int WPROJ = HD * HD;       // 65536
constexpr int WGRU  = G3 * HD;       // 196608
constexpr int WOFF_GRU = 8 * WPROJ;  // 524288
constexpr int WTOT = WOFF_GRU + 4 * WGRU;
constexpr int SMEM_A_BYTES = 2 * 2 * 128 * BKP * 2;   // 40960
constexpr int SMEM_B_BYTES = 2 * 2 * 64 * BKP * 2;    // 20480
constexpr int GEMM_SMEM = SMEM_A_BYTES + SMEM_B_BYTES; // 61440
}

// -------------------------- device scratch ---------------------------------
__device__ float g_atom_f [NB*TNA*HD];
__device__ float g_pharm_f[NB*TNP*HD];
__device__ float g_hyper_f[NB*TNH*HD];
__device__ float g_q1 [NB*TNP*HD];
__device__ float g_k1 [NB*TNH*HD];
__device__ float g_v1 [NB*TNH*HD];
__device__ float g_q2 [NB*TNA*HD];
__device__ float g_k2 [NB*TNP*HD];
__device__ float g_v2 [NB*TNP*HD];
__device__ float g_pharm2[NB*TNP*HD];
__device__ float g_h  [NB*TNA*HD];
__device__ float g_gi_f[(size_t)NB*TNA*G3];
__device__ float g_gi_b[(size_t)NB*TNA*G3];
__device__ float g_hcur[2*NB*HD];
__device__ float g_gh  [2*NB*G3];
__device__ float g_outsum[2*NB*HD];
__device__ int   g_starts[3*(NB+1)];
__device__ int   g_gflags[2][2][12];   // [dir][mt][nt] — monotonic step tags

// bf16 split planes: [0] = hi, [1] = lo
__device__ __nv_bfloat16 g_atom_s [2][NB*TNA*HD];
__device__ __nv_bfloat16 g_pharm_s[2][NB*TNP*HD];
__device__ __nv_bfloat16 g_hyper_s[2][NB*TNH*HD];
__device__ __nv_bfloat16 g_o1_s   [2][NB*TNP*HD];
__device__ __nv_bfloat16 g_pharm2_s[2][NB*TNP*HD];
__device__ __nv_bfloat16 g_o2_s   [2][NB*TNA*HD];
__device__ __nv_bfloat16 g_h_s    [2][NB*TNA*HD];
// ping-pong across GRU steps: [step parity][hi/lo][dir*b*j]
__device__ __nv_bfloat16 g_hcur_s [2][2][2*NB*HD];
__device__ __nv_bfloat16 g_w_s    [2][WTOT];

// -------------------------- helpers ----------------------------------------
__device__ __forceinline__ unsigned s2u(const void* p) {
    return (unsigned)__cvta_generic_to_shared(p);
}
__device__ __forceinline__ void ldmx4(unsigned addr, unsigned& r0, unsigned& r1,
                                      unsigned& r2, unsigned& r3) {
    asm volatile("ldmatrix.sync.aligned.m8n8.x4.shared.b16 {%0,%1,%2,%3}, [%4];"
                 : "=r"(r0), "=r"(r1), "=r"(r2), "=r"(r3) : "r"(addr));
}
__device__ __forceinline__ void mma_bf16(float* c, unsigned a0, unsigned a1,
                                         unsigned a2, unsigned a3,
                                         unsigned b0, unsigned b1) {
    asm volatile(
        "mma.sync.aligned.m16n8k16.row.col.f32.bf16.bf16.f32 "
        "{%0,%1,%2,%3},{%4,%5,%6,%7},{%8,%9},{%0,%1,%2,%3};"
        : "+f"(c[0]), "+f"(c[1]), "+f"(c[2]), "+f"(c[3])
        : "r"(a0), "r"(a1), "r"(a2), "r"(a3), "r"(b0), "r"(b1));
}
__device__ __forceinline__ void split_bf16(float x, __nv_bfloat16& hi, __nv_bfloat16& lo) {
    hi = __float2bfloat16(x);
    lo = __float2bfloat16(x - __bfloat162float(hi));
}
__device__ __forceinline__ void cpa16(unsigned saddr, const void* g) {
    asm volatile("cp.async.cg.shared.global [%0], [%1], 16;" :: "r"(saddr), "l"(g));
}
#define CP_COMMIT() asm volatile("cp.async.commit_group;" ::: "memory")
#define CP_WAIT1()  asm volatile("cp.async.wait_group 1;" ::: "memory")
#define CP_WAIT0()  asm volatile("cp.async.wait_group 0;" ::: "memory")

// -------------------------- batched weight pre-split -------------------------
struct WSrcs { const float* p[12]; };

__global__ void wsplit_all_kernel(WSrcs srcs,
                                  __nv_bfloat16* __restrict__ hi,
                                  __nv_bfloat16* __restrict__ lo) {
    int bid = blockIdx.x;
    int job, local, base, N, K, snk;
    if (bid < 2048) {
        job = bid >> 8;
        local = (bid & 255) * 256 + threadIdx.x;
        base = job * WPROJ; N = HD; K = HD; snk = 0;
    } else {
        int rb = bid - 2048;
        job = 8 + rb / 768;
        local = (rb % 768) * 256 + threadIdx.x;
        base = WOFF_GRU + (job - 8) * WGRU; N = G3; K = HD; snk = 1;
    }
    const float* W = srcs.p[job];
    int n = local / K, k = local - n * K;
    float v = snk ? W[local] : W[(size_t)k * N + n];
    __nv_bfloat16 h, l;
    split_bf16(v, h, l);
    hi[base + local] = h;
    lo[base + local] = l;
}

// -------------------------- prefix sums ------------------------------------
__global__ void prefix_kernel(const int* __restrict__ ac,
                              const int* __restrict__ pc,
                              const int* __restrict__ hc) {
    int w = threadIdx.x;
    if (w < 3) {
        const int* c = (w == 0) ? ac : (w == 1) ? pc : hc;
        int* s = (int*)(g_starts + w * (NB + 1));
        int acc = 0;
        for (int i = 0; i < NB; i++) { s[i] = acc; acc += c[i]; }
        s[NB] = acc;
    }
}

// -------------------------- gather / zero-pad + split ------------------------
__global__ void gather_kernel(const float* __restrict__ msg,
                              const int* __restrict__ counts, int which,
                              float* __restrict__ out,
                              __nv_bfloat16* __restrict__ ohi,
                              __nv_bfloat16* __restrict__ olo, int maxN) {
    int j = blockIdx.x, b = blockIdx.y;
    int cnt = counts[b];
    size_t e = ((size_t)b * maxN + j) * HD + threadIdx.x * 4;
    float4 v = make_float4(0.f, 0.f, 0.f, 0.f);
    if (j < cnt) {
        int src_row = g_starts[which * (NB + 1) + b] + j;
        v = *(const float4*)(msg + (size_t)src_row * HD + threadIdx.x * 4);
    }
    *(float4*)(out + e) = v;
    __nv_bfloat16 h0,l0,h1,l1,h2,l2,h3,l3;
    split_bf16(v.x, h0, l0); split_bf16(v.y, h1, l1);
    split_bf16(v.z, h2, l2); split_bf16(v.w, h3, l3);
    __nv_bfloat162 ha; ha.x = h0; ha.y = h1;
    __nv_bfloat162 hb; hb.x = h2; hb.y = h3;
    __nv_bfloat162 la; la.x = l0; la.y = l1;
    __nv_bfloat162 lb; lb.x = l2; lb.y = l3;
    ((__nv_bfloat162*)(ohi + e))[0] = ha; ((__nv_bfloat162*)(ohi + e))[1] = hb;
    ((__nv_bfloat162*)(olo + e))[0] = la; ((__nv_bfloat162*)(olo + e))[1] = lb;
}

// ---------------------------------------------------------------------------
// pre-split bf16 GEMM with cp.async double buffering (feed-forward version).
// ---------------------------------------------------------------------------
__device__ __forceinline__ void bgemm_pre_body(
    const __nv_bfloat16* __restrict__ Ahi, const __nv_bfloat16* __restrict__ Alo,
    const __nv_bfloat16* __restrict__ Bhi, const __nv_bfloat16* __restrict__ Blo,
    const float* __restrict__ bias, const float* __restrict__ resid,
    float* __restrict__ C, __nv_bfloat16* __restrict__ Chi,
    __nv_bfloat16* __restrict__ Clo,
    int N, int K, int m0, int n0) {

    extern __shared__ __align__(16) char dynsm[];
    __nv_bfloat16 (*As)[2][128][BKP] =
        reinterpret_cast<__nv_bfloat16 (*)[2][128][BKP]>(dynsm);
    __nv_bfloat16 (*Bs)[2][64][BKP] =
        reinterpret_cast<__nv_bfloat16 (*)[2][64][BKP]>(dynsm + SMEM_A_BYTES);

    int tid = threadIdx.x;
    int warp = tid >> 5, lane = tid & 31;
    int wm = (warp & 3) * 32;
    int wn = (warp >> 2) * 32;

    float acc[2][4][4];
#pragma unroll
    for (int i = 0; i < 2; i++)
#pragma unroll
        for (int j = 0; j < 4; j++)
#pragma unroll
            for (int r = 0; r < 4; r++) acc[i][j][r] = 0.f;

    auto load_stage = [&](int s, int k0) {
#pragma unroll
        for (int l = 0; l < 4; l++) {
            int idx = tid + l * 256;
            int plane = idx >> 9, r = idx & 511;
            int row = r >> 2, c16 = r & 3;
            const __nv_bfloat16* src = (plane ? Alo : Ahi) +
                (size_t)(m0 + row) * K + k0 + c16 * 8;
            cpa16(s2u(&As[s][plane][row][c16 * 8]), src);
        }
#pragma unroll
        for (int l = 0; l < 2; l++) {
            int idx = tid + l * 256;
            int plane = idx >> 8, r = idx & 255;
            int row = r >> 2, c16 = r & 3;
            const __nv_bfloat16* src = (plane ? Blo : Bhi) +
                (size_t)(n0 + row) * K + k0 + c16 * 8;
            cpa16(s2u(&Bs[s][plane][row][c16 * 8]), src);
        }
    };

    const int KT = K / 32;
    load_stage(0, 0);
    CP_COMMIT();

    for (int kt = 0; kt < KT; kt++) {
        if (kt + 1 < KT) {
            load_stage((kt + 1) & 1, (kt + 1) * 32);
            CP_COMMIT();
            CP_WAIT1();
        } else {
            CP_WAIT0();
        }
        __syncthreads();

        int s = kt & 1;
        int r = lane & 15, cg = lane >> 4;
#pragma unroll
        for (int kk = 0; kk < 32; kk += 16) {
            unsigned ah[2][4], al[2][4];
#pragma unroll
            for (int mf = 0; mf < 2; mf++) {
                ldmx4(s2u(&As[s][0][wm + mf*16 + r][kk + cg*8]),
                      ah[mf][0], ah[mf][1], ah[mf][2], ah[mf][3]);
                ldmx4(s2u(&As[s][1][wm + mf*16 + r][kk + cg*8]),
                      al[mf][0], al[mf][1], al[mf][2], al[mf][3]);
            }
            unsigned bh[4][2], bl[4][2];
#pragma unroll
            for (int bf = 0; bf < 2; bf++) {
                unsigned q0, q1, q2, q3;
                ldmx4(s2u(&Bs[s][0][wn + bf*16 + r][kk + cg*8]), q0, q1, q2, q3);
                bh[bf*2+0][0] = q0; bh[bf*2+1][0] = q1;
                bh[bf*2+0][1] = q2; bh[bf*2+1][1] = q3;
                ldmx4(s2u(&Bs[s][1][wn + bf*16 + r][kk + cg*8]), q0, q1, q2, q3);
                bl[bf*2+0][0] = q0; bl[bf*2+1][0] = q1;
                bl[bf*2+0][1] = q2; bl[bf*2+1][1] = q3;
            }
#pragma unroll
            for (int mf = 0; mf < 2; mf++)
#pragma unroll
                for (int nf = 0; nf < 4; nf++) {
                    mma_bf16(acc[mf][nf], ah[mf][0], ah[mf][1], ah[mf][2], ah[mf][3],
                             bh[nf][0], bh[nf][1]);
                    mma_bf16(acc[mf][nf], ah[mf][0], ah[mf][1], ah[mf][2], ah[mf][3],
                             bl[nf][0], bl[nf][1]);
                    mma_bf16(acc[mf][nf], al[mf][0], al[mf][1], al[mf][2], al[mf][3],
                             bh[nf][0], bh[nf][1]);
                }
        }
        __syncthreads();
    }

    int g = lane >> 2, tg = lane & 3;
#pragma unroll
    for (int mf = 0; mf < 2; mf++) {
#pragma unroll
        for (int nf = 0; nf < 4; nf++) {
            int c = n0 + wn + nf * 8 + tg * 2;
            int r0 = m0 + wm + mf * 16 + g;
            int r1 = r0 + 8;
            float v0 = acc[mf][nf][0], v1 = acc[mf][nf][1];
            float v2 = acc[mf][nf][2], v3 = acc[mf][nf][3];
            if (bias) { float b0 = bias[c], b1 = bias[c+1];
                        v0 += b0; v1 += b1; v2 += b0; v3 += b1; }
            if (resid) {
                float2 ra = *(const float2*)&resid[(size_t)r0 * N + c];
                float2 rb = *(const float2*)&resid[(size_t)r1 * N + c];
                v0 += ra.x; v1 += ra.y; v2 += rb.x; v3 += rb.y;
            }
            float2 oa; oa.x = v0; oa.y = v1;
            float2 ob; ob.x = v2; ob.y = v3;
            *(float2*)&C[(size_t)r0 * N + c] = oa;
            *(float2*)&C[(size_t)r1 * N + c] = ob;
            if (Chi) {
                __nv_bfloat16 h0,l0,h1,l1;
                split_bf16(v0, h0, l0); split_bf16(v1, h1, l1);
                __nv_bfloat162 hp; hp.x = h0; hp.y = h1;
                __nv_bfloat162 lp; lp.x = l0; lp.y = l1;
                *(__nv_bfloat162*)&Chi[(size_t)r0 * N + c] = hp;
                *(__nv_bfloat162*)&Clo[(size_t)r0 * N + c] = lp;
                split_bf16(v2, h0, l0); split_bf16(v3, h1, l1);
                hp.x = h0; hp.y = h1; lp.x = l0; lp.y = l1;
                *(__nv_bfloat162*)&Chi[(size_t)r1 * N + c] = hp;
                *(__nv_bfloat162*)&Clo[(size_t)r1 * N + c] = lp;
            }
        }
    }
}

__global__ void __launch_bounds__(256)
bgemm_pre_kernel(const __nv_bfloat16* __restrict__ Ahi, const __nv_bfloat16* __restrict__ Alo,
                 const __nv_bfloat16* __restrict__ Bhi, const __nv_bfloat16* __restrict__ Blo,
                 const float* __restrict__ bias, const float* __restrict__ resid,
                 float* __restrict__ C, __nv_bfloat16* __restrict__ Chi,
                 __nv_bfloat16* __restrict__ Clo, int N, int K) {
    bgemm_pre_body(Ahi, Alo, Bhi, Blo, bias, resid, C, Chi, Clo,
                   N, K, blockIdx.y * 128, blockIdx.x * 64);
}

// ---------------------------------------------------------------------------
// GRU step: gh GEMM (grid (12 nt, 2 mt, 2 dir), 256 thr, same tiles as R11)
// + flag-gated gate epilogue in blocks nt<4 using own acc as the r-term.
// hcur bf16 planes ping-pong: GEMM reads set t&1, gate writes set (t+1)&1.
// ---------------------------------------------------------------------------
__global__ void __launch_bounds__(256)
gru_step_kernel(const float* __restrict__ bhh_f, const float* __restrict__ bhh_b,
                const int* __restrict__ counts, int t) {
    extern __shared__ __align__(16) char dynsm[];
    __nv_bfloat16 (*As)[2][128][BKP] =
        reinterpret_cast<__nv_bfloat16 (*)[2][128][BKP]>(dynsm);
    __nv_bfloat16 (*Bs)[2][64][BKP] =
        reinterpret_cast<__nv_bfloat16 (*)[2][64][BKP]>(dynsm + SMEM_A_BYTES);

    int nt = blockIdx.x, mt = blockIdx.y, d = blockIdx.z;
    int tid = threadIdx.x;
    int warp = tid >> 5, lane = tid & 31;
    int wm = (warp & 3) * 32;
    int wn = (warp >> 2) * 32;
    int rdset = t & 1, wrset = (t + 1) & 1;
    int m0 = mt * 128, n0 = nt * 64;

    const __nv_bfloat16* Ahi = g_hcur_s[rdset][0] + (size_t)d * NB * HD;
    const __nv_bfloat16* Alo = g_hcur_s[rdset][1] + (size_t)d * NB * HD;
    size_t woff = WOFF_GRU + (d ? 3 : 1) * (size_t)WGRU;
    const __nv_bfloat16* Bhi = g_w_s[0] + woff;
    const __nv_bfloat16* Blo = g_w_s[1] + woff;

    float acc[2][4][4];
#pragma unroll
    for (int i = 0; i < 2; i++)
#pragma unroll
        for (int j = 0; j < 4; j++)
#pragma unroll
            for (int r = 0; r < 4; r++) acc[i][j][r] = 0.f;

    auto load_stage = [&](int s, int k0) {
#pragma unroll
        for (int l = 0; l < 4; l++) {
            int idx = tid + l * 256;
            int plane = idx >> 9, r = idx & 511;
            int row = r >> 2, c16 = r & 3;
            const __nv_bfloat16* src = (plane ? Alo : Ahi) +
                (size_t)(m0 + row) * HD + k0 + c16 * 8;
            cpa16(s2u(&As[s][plane][row][c16 * 8]), src);
        }
#pragma unroll
        for (int l = 0; l < 2; l++) {
            int idx = tid + l * 256;
            int plane = idx >> 8, r = idx & 255;
            int row = r >> 2, c16 = r & 3;
            const __nv_bfloat16* src = (plane ? Blo : Bhi) +
                (size_t)(n0 + row) * HD + k0 + c16 * 8;
            cpa16(s2u(&Bs[s][plane][row][c16 * 8]), src);
        }
    };

    const int KT = HD / 32;
    load_stage(0, 0);
    CP_COMMIT();

    for (int kt = 0; kt < KT; kt++) {
        if (kt + 1 < KT) {
            load_stage((kt + 1) & 1, (kt + 1) * 32);
            CP_COMMIT();
            CP_WAIT1();
        } else {
            CP_WAIT0();
        }
        __syncthreads();

        int s = kt & 1;
        int r = lane & 15, cg = lane >> 4;
#pragma unroll
        for (int kk = 0; kk < 32; kk += 16) {
            unsigned ah[2][4], al[2][4];
#pragma unroll
            for (int mf = 0; mf < 2; mf++) {
                ldmx4(s2u(&As[s][0][wm + mf*16 + r][kk + cg*8]),
                      ah[mf][0], ah[mf][1], ah[mf][2], ah[mf][3]);
                ldmx4(s2u(&As[s][1][wm + mf*16 + r][kk + cg*8]),
                      al[mf][0], al[mf][1], al[mf][2], al[mf][3]);
            }
            unsigned bh[4][2], bl[4][2];
#pragma unroll
            for (int bf = 0; bf < 2; bf++) {
                unsigned q0, q1, q2, q3;
                ldmx4(s2u(&Bs[s][0][wn + bf*16 + r][kk + cg*8]), q0, q1, q2, q3);
                bh[bf*2+0][0] = q0; bh[bf*2+1][0] = q1;
                bh[bf*2+0][1] = q2; bh[bf*2+1][1] = q3;
                ldmx4(s2u(&Bs[s][1][wn + bf*16 + r][kk + cg*8]), q0, q1, q2, q3);
                bl[bf*2+0][0] = q0; bl[bf*2+1][0] = q1;
                bl[bf*2+0][1] = q2; bl[bf*2+1][1] = q3;
            }
#pragma unroll
            for (int mf = 0; mf < 2; mf++)
#pragma unroll
                for (int nf = 0; nf < 4; nf++) {
                    mma_bf16(acc[mf][nf], ah[mf][0], ah[mf][1], ah[mf][2], ah[mf][3],
                             bh[nf][0], bh[nf][1]);
                    mma_bf16(acc[mf][nf], ah[mf][0], ah[mf][1], ah[mf][2], ah[mf][3],
                             bl[nf][0], bl[nf][1]);
                    mma_bf16(acc[mf][nf], al[mf][0], al[mf][1], al[mf][2], al[mf][3],
                             bh[nf][0], bh[nf][1]);
                }
        }
        __syncthreads();
    }

    int g = lane >> 2, tg = lane & 3;
    float* ghbase = g_gh + (size_t)d * NB * G3;

    if (nt >= 4) {
        // producer tiles (z / n gates): write gh, fence, raise flag
#pragma unroll
        for (int mf = 0; mf < 2; mf++) {
#pragma unroll
            for (int nf = 0; nf < 4; nf++) {
                int c = n0 + wn + nf * 8 + tg * 2;
                int r0 = m0 + wm + mf * 16 + g;
                int r1 = r0 + 8;
                float2 oa; oa.x = acc[mf][nf][0]; oa.y = acc[mf][nf][1];
                float2 ob; ob.x = acc[mf][nf][2]; ob.y = acc[mf][nf][3];
                *(float2*)&ghbase[(size_t)r0 * G3 + c] = oa;
                *(float2*)&ghbase[(size_t)r1 * G3 + c] = ob;
            }
        }
        __threadfence();
        __syncthreads();
        if (tid == 0) atomicExch(&g_gflags[d][mt][nt], t + 1);
        return;
    }

    // consumer tiles (r gate, j in [0,256)): wait for z and n tiles
    if (tid == 0) {
        while (atomicAdd(&g_gflags[d][mt][nt + 4], 0) < t + 1) {}
        while (atomicAdd(&g_gflags[d][mt][nt + 8], 0) < t + 1) {}
    }
    __syncthreads();
    __threadfence();

    const float* bhh = d ? bhh_b : bhh_f;
    const float* gib = d ? g_gi_b : g_gi_f;
    int teff = d ? (TNA - 1 - t) : t;

#pragma unroll
    for (int mf = 0; mf < 2; mf++) {
#pragma unroll
        for (int nf = 0; nf < 4; nf++) {
#pragma unroll
            for (int hv = 0; hv < 2; hv++) {      // half: row r0 or r1
                int b = m0 + wm + mf * 16 + g + hv * 8;
#pragma unroll
                for (int cc = 0; cc < 2; cc++) {
                    int jg = n0 + wn + nf * 8 + tg * 2 + cc;
                    float rterm = acc[mf][nf][hv * 2 + cc];
                    float hz = ghbase[(size_t)b * G3 + jg + 256] + bhh[jg + 256];
                    float hn = ghbase[(size_t)b * G3 + jg + 512] + bhh[jg + 512];
                    const float* gi = gib + ((size_t)b * TNA + teff) * G3 + jg;
                    float r_ = 1.f / (1.f + expf(-(gi[0] + rterm + bhh[jg])));
                    float z  = 1.f / (1.f + expf(-(gi[256] + hz)));
                    float n  = tanhf(gi[512] + r_ * hn);
                    size_t hidx = (size_t)d * NB * HD + (size_t)b * HD + jg;
                    float hp = g_hcur[hidx];
                    float h = (1.f - z) * n + z * hp;
                    g_hcur[hidx] = h;
                    __nv_bfloat16 hh, hl;
                    split_bf16(h, hh, hl);
                    g_hcur_s[wrset][0][hidx] = hh;
                    g_hcur_s[wrset][1][hidx] = hl;
                    if (teff < counts[b]) g_outsum[hidx] += h;
                }
            }
        }
    }
}

// -------------------------- attention (fp32 in, split out) -------------------
template <int LQ, int LK>
__global__ void attn_kernel(const float* __restrict__ qh,
                            const float* __restrict__ kh,
                            const float* __restrict__ vh,
                            const int* __restrict__ qc,
                            const int* __restrict__ kc,
                            __nv_bfloat16* __restrict__ ohi,
                            __nv_bfloat16* __restrict__ olo) {
    __shared__ float ks[LK * DKH];
    __shared__ float vs[LK * DKH];
    int bh = blockIdx.x;
    int b = bh / NHEAD, hd = bh % NHEAD;
    for (int idx = threadIdx.x; idx < LK * DKH; idx += blockDim.x) {
        int k = idx / DKH, i = idx % DKH;
        size_t base = ((size_t)(b * LK) + k) * HD + hd * DKH + i;
        ks[idx] = kh[base];
        vs[idx] = vh[base];
    }
    __syncthreads();
    int q = threadIdx.x;
    if (q >= LQ) return;

    float qreg[DKH];
    const float* qp = &qh[((size_t)(b * LQ) + q) * HD + hd * DKH];
#pragma unroll
    for (int i = 0; i < DKH; i++) qreg[i] = qp[i];

    bool vq = q < qc[b];
    int kcnt = kc[b];
    float s[LK];
    float mx = -3.402823e38f;
#pragma unroll
    for (int k = 0; k < LK; k++) {
        float dd = 0.f;
#pragma unroll
        for (int i = 0; i < DKH; i++) dd = fmaf(qreg[i], ks[k * DKH + i], dd);
        float val = (vq && k < kcnt) ? dd * 0.125f : -1e9f;
        s[k] = val;
        mx = fmaxf(mx, val);
    }
    float sum = 0.f;
#pragma unroll
    for (int k = 0; k < LK; k++) { s[k] = expf(s[k] - mx); sum += s[k]; }
    float inv = 1.f / sum;
    size_t obase = ((size_t)(b * LQ) + q) * HD + hd * DKH;
#pragma unroll
    for (int i = 0; i < DKH; i++) {
        float a = 0.f;
#pragma unroll
        for (int k = 0; k < LK; k++) a = fmaf(s[k], vs[k * DKH + i], a);
        a *= inv;
        __nv_bfloat16 h, l;
        split_bf16(a, h, l);
        ohi[obase + i] = h;
        olo[obase + i] = l;
    }
}

// -------------------------- h0 = max over t (+ split) ------------------------
__global__ void hmax_kernel() {
    int b = blockIdx.x, j = threadIdx.x;
    float m = -3.402823e38f;
    for (int t = 0; t < TNA; t++)
        m = fmaxf(m, g_h[((size_t)(b * TNA) + t) * HD + j]);
    size_t i0 = (size_t)b * HD + j;
    size_t i1 = (size_t)NB * HD + i0;
    g_hcur[i0] = m; g_hcur[i1] = m;
    __nv_bfloat16 h, l;
    split_bf16(m, h, l);
    g_hcur_s[0][0][i0] = h; g_hcur_s[0][0][i1] = h;
    g_hcur_s[0][1][i0] = l; g_hcur_s[0][1][i1] = l;
}

__global__ void zero_outsum_kernel() {
    int idx = blockIdx.x * blockDim.x + threadIdx.x;
    g_outsum[idx] = 0.f;
    if (idx < 48) ((int*)g_gflags)[idx] = 0;
}

__global__ void final_kernel(const int* __restrict__ counts, float* __restrict__ out) {
    int idx = blockIdx.x * blockDim.x + threadIdx.x;
    int d = idx >> 16;
    int b = (idx >> 8) & 255;
    int j = idx & 255;
    float c = (float)counts[b];
    out[(size_t)b * 512 + d * 256 + j] =
        g_outsum[(size_t)d * NB * HD + (size_t)b * HD + j] / c;
}

// -------------------------- host launch -------------------------------------
template <typename T>
static T* symaddr(const void* sym) {
    void* p = nullptr;
    cudaGetSymbolAddress(&p, sym);
    return (T*)p;
}

extern "C" void kernel_launch(void* const* d_in, const int* in_sizes, int n_in,
                              void* d_out, int out_size) {
    int wbase, ci0, ci1, ci2;
    if (in_sizes[3] == NB) { ci0 = 3; ci1 = 4; ci2 = 5; wbase = 6; }
    else { wbase = 3; ci0 = n_in - 3; ci1 = n_in - 2; ci2 = n_in - 1; }

    const float* atom_msg  = (const float*)d_in[0];
    const float* pharm_msg = (const float*)d_in[1];
    const float* hyper_msg = (const float*)d_in[2];
    const int* ac = (const int*)d_in[ci0];
    const int* pc = (const int*)d_in[ci1];
    const int* hc = (const int*)d_in[ci2];

    const float* p2h[8];
    const float* a2p[8];
    for (int i = 0; i < 8; i++) p2h[i] = (const float*)d_in[wbase + i];
    for (int i = 0; i < 8; i++) a2p[i] = (const float*)d_in[wbase + 8 + i];
    const float* Wih_f = (const float*)d_in[wbase + 16];
    const float* Whh_f = (const float*)d_in[wbase + 17];
    const float* bih_f = (const float*)d_in[wbase + 18];
    const float* bhh_f = (const float*)d_in[wbase + 19];
    const float* Wih_b = (const float*)d_in[wbase + 20];
    const float* Whh_b = (const float*)d_in[wbase + 21];
    const float* bih_b = (const float*)d_in[wbase + 22];
    const float* bhh_b = (const float*)d_in[wbase + 23];

    float* atom_f  = symaddr<float>(g_atom_f);
    float* pharm_f = symaddr<float>(g_pharm_f);
    float* hyper_f = symaddr<float>(g_hyper_f);
    float* q1 = symaddr<float>(g_q1);
    float* k1 = symaddr<float>(g_k1);
    float* v1 = symaddr<float>(g_v1);
    float* q2 = symaddr<float>(g_q2);
    float* k2 = symaddr<float>(g_k2);
    float* v2 = symaddr<float>(g_v2);
    float* pharm2 = symaddr<float>(g_pharm2);
    float* hbuf = symaddr<float>(g_h);
    float* gi_f = symaddr<float>(g_gi_f);
    float* gi_b = symaddr<float>(g_gi_b);

    __nv_bfloat16* atom_s  = symaddr<__nv_bfloat16>(g_atom_s);
    __nv_bfloat16* pharm_s = symaddr<__nv_bfloat16>(g_pharm_s);
    __nv_bfloat16* hyper_s = symaddr<__nv_bfloat16>(g_hyper_s);
    __nv_bfloat16* o1_s    = symaddr<__nv_bfloat16>(g_o1_s);
    __nv_bfloat16* pharm2_s= symaddr<__nv_bfloat16>(g_pharm2_s);
    __nv_bfloat16* o2_s    = symaddr<__nv_bfloat16>(g_o2_s);
    __nv_bfloat16* h_s     = symaddr<__nv_bfloat16>(g_h_s);
    __nv_bfloat16* w_s     = symaddr<__nv_bfloat16>(g_w_s);

    const size_t SA = (size_t)NB*TNA*HD;
    const size_t SP = (size_t)NB*TNP*HD;
    const size_t SH = (size_t)NB*TNH*HD;
    __nv_bfloat16 *atom_hi = atom_s,   *atom_lo = atom_s + SA;
    __nv_bfloat16 *pharm_hi = pharm_s, *pharm_lo = pharm_s + SP;
    __nv_bfloat16 *hyper_hi = hyper_s, *hyper_lo = hyper_s + SH;
    __nv_bfloat16 *o1_hi = o1_s,       *o1_lo = o1_s + SP;
    __nv_bfloat16 *pharm2_hi = pharm2_s, *pharm2_lo = pharm2_s + SP;
    __nv_bfloat16 *o2_hi = o2_s,       *o2_lo = o2_s + SA;
    __nv_bfloat16 *h_hi = h_s,         *h_lo = h_s + SA;
    __nv_bfloat16 *w_hi = w_s,         *w_lo = w_s + WTOT;

    float* out = (float*)d_out;

    const int MA = NB * TNA;   // 32512 = 254*128
    const int MP = NB * TNP;   // 5888  = 46*128
    const int MH = NB * TNH;   // 2816  = 22*128

    cudaFuncSetAttribute(bgemm_pre_kernel,
                         cudaFuncAttributeMaxDynamicSharedMemorySize, GEMM_SMEM);
    cudaFuncSetAttribute(gru_step_kernel,
                         cudaFuncAttributeMaxDynamicSharedMemorySize, GEMM_SMEM);

    prefix_kernel<<<1, 32>>>(ac, pc, hc);

    // ---- pre-split all 12 weight matrices in one batched launch ----
    WSrcs ws;
    ws.p[0] = p2h[0]; ws.p[1] = p2h[2]; ws.p[2] = p2h[4]; ws.p[3] = p2h[6];
    ws.p[4] = a2p[0]; ws.p[5] = a2p[2]; ws.p[6] = a2p[4]; ws.p[7] = a2p[6];
    ws.p[8] = Wih_f;  ws.p[9] = Whh_f;  ws.p[10] = Wih_b; ws.p[11] = Whh_b;
    wsplit_all_kernel<<<2048 + 4 * 768, 256>>>(ws, w_hi, w_lo);

    // ---- gathers (+split) ----
    gather_kernel<<<dim3(TNA, NB), 64>>>(atom_msg,  ac, 0, atom_f,  atom_hi,  atom_lo,  TNA);
    gather_kernel<<<dim3(TNP, NB), 64>>>(pharm_msg, pc, 1, pharm_f, pharm_hi, pharm_lo, TNP);
    gather_kernel<<<dim3(TNH, NB), 64>>>(hyper_msg, hc, 2, hyper_f, hyper_hi, hyper_lo, TNH);

    // ---- MHA1 ----
    bgemm_pre_kernel<<<dim3(HD/64, MP/128), 256, GEMM_SMEM>>>(pharm_hi, pharm_lo,
        w_hi + 0*WPROJ, w_lo + 0*WPROJ, p2h[1], nullptr, q1, nullptr, nullptr, HD, HD);
    bgemm_pre_kernel<<<dim3(HD/64, MH/128), 256, GEMM_SMEM>>>(hyper_hi, hyper_lo,
        w_hi + 1*WPROJ, w_lo + 1*WPROJ, p2h[3], nullptr, k1, nullptr, nullptr, HD, HD);
    bgemm_pre_kernel<<<dim3(HD/64, MH/128), 256, GEMM_SMEM>>>(hyper_hi, hyper_lo,
        w_hi + 2*WPROJ, w_lo + 2*WPROJ, p2h[5], nullptr, v1, nullptr, nullptr, HD, HD);
    attn_kernel<TNP, TNH><<<NB * NHEAD, 32>>>(q1, k1, v1, pc, hc, o1_hi, o1_lo);
    bgemm_pre_kernel<<<dim3(HD/64, MP/128), 256, GEMM_SMEM>>>(o1_hi, o1_lo,
        w_hi + 3*WPROJ, w_lo + 3*WPROJ, p2h[7], pharm_f, pharm2, pharm2_hi, pharm2_lo, HD, HD);

    // ---- MHA2 ----
    bgemm_pre_kernel<<<dim3(HD/64, MA/128), 256, GEMM_SMEM>>>(atom_hi, atom_lo,
        w_hi + 4*WPROJ, w_lo + 4*WPROJ, a2p[1], nullptr, q2, nullptr, nullptr, HD, HD);
    bgemm_pre_kernel<<<dim3(HD/64, MP/128), 256, GEMM_SMEM>>>(pharm2_hi, pharm2_lo,
        w_hi + 5*WPROJ, w_lo + 5*WPROJ, a2p[3], nullptr, k2, nullptr, nullptr, HD, HD);
    bgemm_pre_kernel<<<dim3(HD/64, MP/128), 256, GEMM_SMEM>>>(pharm2_hi, pharm2_lo,
        w_hi + 6*WPROJ, w_lo + 6*WPROJ, a2p[5], nullptr, v2, nullptr, nullptr, HD, HD);
    attn_kernel<TNA, TNP><<<NB * NHEAD, 128>>>(q2, k2, v2, ac, pc, o2_hi, o2_lo);
    bgemm_pre_kernel<<<dim3(HD/64, MA/128), 256, GEMM_SMEM>>>(o2_hi, o2_lo,
        w_hi + 7*WPROJ, w_lo + 7*WPROJ, a2p[7], atom_f, hbuf, h_hi, h_lo, HD, HD);

    // ---- h0 = max over t ----
    hmax_kernel<<<NB, HD>>>();

    // ---- gi = h @ Wih^T + bih ----
    bgemm_pre_kernel<<<dim3(G3/64, MA/128), 256, GEMM_SMEM>>>(h_hi, h_lo,
        w_hi + WOFF_GRU + 0*WGRU, w_lo + WOFF_GRU + 0*WGRU, bih_f, nullptr,
        gi_f, nullptr, nullptr, G3, HD);
    bgemm_pre_kernel<<<dim3(G3/64, MA/128), 256, GEMM_SMEM>>>(h_hi, h_lo,
        w_hi + WOFF_GRU + 2*WGRU, w_lo + WOFF_GRU + 2*WGRU, bih_b, nullptr,
        gi_b, nullptr, nullptr, G3, HD);

    // ---- GRU recurrence: ONE kernel per step (flag-gated gate epilogue) ----
    zero_outsum_kernel<<<(2 * NB * HD) / 256, 256>>>();
    for (int t = 0; t < TNA; t++) {
        gru_step_kernel<<<dim3(12, 2, 2), 256, GEMM_SMEM>>>(bhh_f, bhh_b, ac, t);
    }

    final_kernel<<<(2 * NB * HD) / 256, 256>>>(ac, out);
    (void)out_size; (void)n_in;
}

// round 17
// speedup vs baseline: 4.1226x; 4.1226x over previous
#include <cuda_runtime.h>
#include <cuda_bf16.h>
#include <math.h>

// ---------------------------------------------------------------------------
// HyperGraphEncoder — split-bf16 mma.sync, pre-split operands, cp.async GEMMs.
// Recurrence: per-step GEMM (96 x 64x64 tiles) + vectorized gate kernel.
// ---------------------------------------------------------------------------

namespace {
constexpr int NB   = 256;
constexpr int HD   = 256;
constexpr int NHEAD = 4;
constexpr int DKH  = 64;
constexpr int TNA  = 127;
constexpr int TNP  = 23;
constexpr int TNH  = 11;
constexpr int G3   = 768;
constexpr int BKP  = 40;             // padded bf16 k-stride in smem
constexpr int WPROJ = HD * HD;       // 65536
constexpr int WGRU  = G3 * HD;       // 196608
constexpr int WOFF_GRU = 8 * WPROJ;  // 524288
constexpr int WTOT = WOFF_GRU + 4 * WGRU;
constexpr int SMEM_A_BYTES = 2 * 2 * 128 * BKP * 2;   // 40960
constexpr int SMEM_B_BYTES = 2 * 2 * 64 * BKP * 2;    // 20480
constexpr int GEMM_SMEM = SMEM_A_BYTES + SMEM_B_BYTES; // 61440
// gru 64-row-tile GEMM smem
constexpr int SMEM_A64 = 2 * 2 * 64 * BKP * 2;        // 20480
constexpr int GRU_SMEM = SMEM_A64 + SMEM_B_BYTES;     // 40960
}

// -------------------------- device scratch ---------------------------------
__device__ float g_atom_f [NB*TNA*HD];
__device__ float g_pharm_f[NB*TNP*HD];
__device__ float g_hyper_f[NB*TNH*HD];
__device__ float g_q1 [NB*TNP*HD];
__device__ float g_k1 [NB*TNH*HD];
__device__ float g_v1 [NB*TNH*HD];
__device__ float g_q2 [NB*TNA*HD];
__device__ float g_k2 [NB*TNP*HD];
__device__ float g_v2 [NB*TNP*HD];
__device__ float g_pharm2[NB*TNP*HD];
__device__ float g_h  [NB*TNA*HD];
__device__ float g_gi_f[(size_t)NB*TNA*G3];
__device__ float g_gi_b[(size_t)NB*TNA*G3];
__device__ float g_hcur[2*NB*HD];
__device__ float g_gh  [2*NB*G3];
__device__ float g_outsum[2*NB*HD];
__device__ int   g_starts[3*(NB+1)];

// bf16 split planes: [0] = hi, [1] = lo
__device__ __nv_bfloat16 g_atom_s [2][NB*TNA*HD];
__device__ __nv_bfloat16 g_pharm_s[2][NB*TNP*HD];
__device__ __nv_bfloat16 g_hyper_s[2][NB*TNH*HD];
__device__ __nv_bfloat16 g_o1_s   [2][NB*TNP*HD];
__device__ __nv_bfloat16 g_pharm2_s[2][NB*TNP*HD];
__device__ __nv_bfloat16 g_o2_s   [2][NB*TNA*HD];
__device__ __nv_bfloat16 g_h_s    [2][NB*TNA*HD];
__device__ __nv_bfloat16 g_hcur_s [2][2*NB*HD];
__device__ __nv_bfloat16 g_w_s    [2][WTOT];

// -------------------------- helpers ----------------------------------------
__device__ __forceinline__ unsigned s2u(const void* p) {
    return (unsigned)__cvta_generic_to_shared(p);
}
__device__ __forceinline__ void ldmx4(unsigned addr, unsigned& r0, unsigned& r1,
                                      unsigned& r2, unsigned& r3) {
    asm volatile("ldmatrix.sync.aligned.m8n8.x4.shared.b16 {%0,%1,%2,%3}, [%4];"
                 : "=r"(r0), "=r"(r1), "=r"(r2), "=r"(r3) : "r"(addr));
}
__device__ __forceinline__ void mma_bf16(float* c, unsigned a0, unsigned a1,
                                         unsigned a2, unsigned a3,
                                         unsigned b0, unsigned b1) {
    asm volatile(
        "mma.sync.aligned.m16n8k16.row.col.f32.bf16.bf16.f32 "
        "{%0,%1,%2,%3},{%4,%5,%6,%7},{%8,%9},{%0,%1,%2,%3};"
        : "+f"(c[0]), "+f"(c[1]), "+f"(c[2]), "+f"(c[3])
        : "r"(a0), "r"(a1), "r"(a2), "r"(a3), "r"(b0), "r"(b1));
}
__device__ __forceinline__ void split_bf16(float x, __nv_bfloat16& hi, __nv_bfloat16& lo) {
    hi = __float2bfloat16(x);
    lo = __float2bfloat16(x - __bfloat162float(hi));
}
__device__ __forceinline__ void cpa16(unsigned saddr, const void* g) {
    asm volatile("cp.async.cg.shared.global [%0], [%1], 16;" :: "r"(saddr), "l"(g));
}
#define CP_COMMIT() asm volatile("cp.async.commit_group;" ::: "memory")
#define CP_WAIT1()  asm volatile("cp.async.wait_group 1;" ::: "memory")
#define CP_WAIT0()  asm volatile("cp.async.wait_group 0;" ::: "memory")

// -------------------------- batched weight pre-split -------------------------
struct WSrcs { const float* p[12]; };

__global__ void wsplit_all_kernel(WSrcs srcs,
                                  __nv_bfloat16* __restrict__ hi,
                                  __nv_bfloat16* __restrict__ lo) {
    int bid = blockIdx.x;
    int job, local, base, N, K, snk;
    if (bid < 2048) {
        job = bid >> 8;
        local = (bid & 255) * 256 + threadIdx.x;
        base = job * WPROJ; N = HD; K = HD; snk = 0;
    } else {
        int rb = bid - 2048;
        job = 8 + rb / 768;
        local = (rb % 768) * 256 + threadIdx.x;
        base = WOFF_GRU + (job - 8) * WGRU; N = G3; K = HD; snk = 1;
    }
    const float* W = srcs.p[job];
    int n = local / K, k = local - n * K;
    float v = snk ? W[local] : W[(size_t)k * N + n];
    __nv_bfloat16 h, l;
    split_bf16(v, h, l);
    hi[base + local] = h;
    lo[base + local] = l;
}

// -------------------------- prefix sums ------------------------------------
__global__ void prefix_kernel(const int* __restrict__ ac,
                              const int* __restrict__ pc,
                              const int* __restrict__ hc) {
    int w = threadIdx.x;
    if (w < 3) {
        const int* c = (w == 0) ? ac : (w == 1) ? pc : hc;
        int* s = (int*)(g_starts + w * (NB + 1));
        int acc = 0;
        for (int i = 0; i < NB; i++) { s[i] = acc; acc += c[i]; }
        s[NB] = acc;
    }
}

// -------------------------- gather / zero-pad + split ------------------------
__global__ void gather_kernel(const float* __restrict__ msg,
                              const int* __restrict__ counts, int which,
                              float* __restrict__ out,
                              __nv_bfloat16* __restrict__ ohi,
                              __nv_bfloat16* __restrict__ olo, int maxN) {
    int j = blockIdx.x, b = blockIdx.y;
    int cnt = counts[b];
    size_t e = ((size_t)b * maxN + j) * HD + threadIdx.x * 4;
    float4 v = make_float4(0.f, 0.f, 0.f, 0.f);
    if (j < cnt) {
        int src_row = g_starts[which * (NB + 1) + b] + j;
        v = *(const float4*)(msg + (size_t)src_row * HD + threadIdx.x * 4);
    }
    *(float4*)(out + e) = v;
    __nv_bfloat16 h0,l0,h1,l1,h2,l2,h3,l3;
    split_bf16(v.x, h0, l0); split_bf16(v.y, h1, l1);
    split_bf16(v.z, h2, l2); split_bf16(v.w, h3, l3);
    __nv_bfloat162 ha; ha.x = h0; ha.y = h1;
    __nv_bfloat162 hb; hb.x = h2; hb.y = h3;
    __nv_bfloat162 la; la.x = l0; la.y = l1;
    __nv_bfloat162 lb; lb.x = l2; lb.y = l3;
    ((__nv_bfloat162*)(ohi + e))[0] = ha; ((__nv_bfloat162*)(ohi + e))[1] = hb;
    ((__nv_bfloat162*)(olo + e))[0] = la; ((__nv_bfloat162*)(olo + e))[1] = lb;
}

// ---------------------------------------------------------------------------
// pre-split bf16 GEMM with cp.async double buffering (feed-forward).
// Block 128M x 64N, BK=32, 256 threads (8 warps = 4m x 2n of 32x32).
// ---------------------------------------------------------------------------
__device__ __forceinline__ void bgemm_pre_body(
    const __nv_bfloat16* __restrict__ Ahi, const __nv_bfloat16* __restrict__ Alo,
    const __nv_bfloat16* __restrict__ Bhi, const __nv_bfloat16* __restrict__ Blo,
    const float* __restrict__ bias, const float* __restrict__ resid,
    float* __restrict__ C, __nv_bfloat16* __restrict__ Chi,
    __nv_bfloat16* __restrict__ Clo,
    int N, int K, int m0, int n0) {

    extern __shared__ __align__(16) char dynsm[];
    __nv_bfloat16 (*As)[2][128][BKP] =
        reinterpret_cast<__nv_bfloat16 (*)[2][128][BKP]>(dynsm);
    __nv_bfloat16 (*Bs)[2][64][BKP] =
        reinterpret_cast<__nv_bfloat16 (*)[2][64][BKP]>(dynsm + SMEM_A_BYTES);

    int tid = threadIdx.x;
    int warp = tid >> 5, lane = tid & 31;
    int wm = (warp & 3) * 32;
    int wn = (warp >> 2) * 32;

    float acc[2][4][4];
#pragma unroll
    for (int i = 0; i < 2; i++)
#pragma unroll
        for (int j = 0; j < 4; j++)
#pragma unroll
            for (int r = 0; r < 4; r++) acc[i][j][r] = 0.f;

    auto load_stage = [&](int s, int k0) {
#pragma unroll
        for (int l = 0; l < 4; l++) {
            int idx = tid + l * 256;
            int plane = idx >> 9, r = idx & 511;
            int row = r >> 2, c16 = r & 3;
            const __nv_bfloat16* src = (plane ? Alo : Ahi) +
                (size_t)(m0 + row) * K + k0 + c16 * 8;
            cpa16(s2u(&As[s][plane][row][c16 * 8]), src);
        }
#pragma unroll
        for (int l = 0; l < 2; l++) {
            int idx = tid + l * 256;
            int plane = idx >> 8, r = idx & 255;
            int row = r >> 2, c16 = r & 3;
            const __nv_bfloat16* src = (plane ? Blo : Bhi) +
                (size_t)(n0 + row) * K + k0 + c16 * 8;
            cpa16(s2u(&Bs[s][plane][row][c16 * 8]), src);
        }
    };

    const int KT = K / 32;
    load_stage(0, 0);
    CP_COMMIT();

    for (int kt = 0; kt < KT; kt++) {
        if (kt + 1 < KT) {
            load_stage((kt + 1) & 1, (kt + 1) * 32);
            CP_COMMIT();
            CP_WAIT1();
        } else {
            CP_WAIT0();
        }
        __syncthreads();

        int s = kt & 1;
        int r = lane & 15, cg = lane >> 4;
#pragma unroll
        for (int kk = 0; kk < 32; kk += 16) {
            unsigned ah[2][4], al[2][4];
#pragma unroll
            for (int mf = 0; mf < 2; mf++) {
                ldmx4(s2u(&As[s][0][wm + mf*16 + r][kk + cg*8]),
                      ah[mf][0], ah[mf][1], ah[mf][2], ah[mf][3]);
                ldmx4(s2u(&As[s][1][wm + mf*16 + r][kk + cg*8]),
                      al[mf][0], al[mf][1], al[mf][2], al[mf][3]);
            }
            unsigned bh[4][2], bl[4][2];
#pragma unroll
            for (int bf = 0; bf < 2; bf++) {
                unsigned q0, q1, q2, q3;
                ldmx4(s2u(&Bs[s][0][wn + bf*16 + r][kk + cg*8]), q0, q1, q2, q3);
                bh[bf*2+0][0] = q0; bh[bf*2+1][0] = q1;
                bh[bf*2+0][1] = q2; bh[bf*2+1][1] = q3;
                ldmx4(s2u(&Bs[s][1][wn + bf*16 + r][kk + cg*8]), q0, q1, q2, q3);
                bl[bf*2+0][0] = q0; bl[bf*2+1][0] = q1;
                bl[bf*2+0][1] = q2; bl[bf*2+1][1] = q3;
            }
#pragma unroll
            for (int mf = 0; mf < 2; mf++)
#pragma unroll
                for (int nf = 0; nf < 4; nf++) {
                    mma_bf16(acc[mf][nf], ah[mf][0], ah[mf][1], ah[mf][2], ah[mf][3],
                             bh[nf][0], bh[nf][1]);
                    mma_bf16(acc[mf][nf], ah[mf][0], ah[mf][1], ah[mf][2], ah[mf][3],
                             bl[nf][0], bl[nf][1]);
                    mma_bf16(acc[mf][nf], al[mf][0], al[mf][1], al[mf][2], al[mf][3],
                             bh[nf][0], bh[nf][1]);
                }
        }
        __syncthreads();
    }

    int g = lane >> 2, tg = lane & 3;
#pragma unroll
    for (int mf = 0; mf < 2; mf++) {
#pragma unroll
        for (int nf = 0; nf < 4; nf++) {
            int c = n0 + wn + nf * 8 + tg * 2;
            int r0 = m0 + wm + mf * 16 + g;
            int r1 = r0 + 8;
            float v0 = acc[mf][nf][0], v1 = acc[mf][nf][1];
            float v2 = acc[mf][nf][2], v3 = acc[mf][nf][3];
            if (bias) { float b0 = bias[c], b1 = bias[c+1];
                        v0 += b0; v1 += b1; v2 += b0; v3 += b1; }
            if (resid) {
                float2 ra = *(const float2*)&resid[(size_t)r0 * N + c];
                float2 rb = *(const float2*)&resid[(size_t)r1 * N + c];
                v0 += ra.x; v1 += ra.y; v2 += rb.x; v3 += rb.y;
            }
            float2 oa; oa.x = v0; oa.y = v1;
            float2 ob; ob.x = v2; ob.y = v3;
            *(float2*)&C[(size_t)r0 * N + c] = oa;
            *(float2*)&C[(size_t)r1 * N + c] = ob;
            if (Chi) {
                __nv_bfloat16 h0,l0,h1,l1;
                split_bf16(v0, h0, l0); split_bf16(v1, h1, l1);
                __nv_bfloat162 hp; hp.x = h0; hp.y = h1;
                __nv_bfloat162 lp; lp.x = l0; lp.y = l1;
                *(__nv_bfloat162*)&Chi[(size_t)r0 * N + c] = hp;
                *(__nv_bfloat162*)&Clo[(size_t)r0 * N + c] = lp;
                split_bf16(v2, h0, l0); split_bf16(v3, h1, l1);
                hp.x = h0; hp.y = h1; lp.x = l0; lp.y = l1;
                *(__nv_bfloat162*)&Chi[(size_t)r1 * N + c] = hp;
                *(__nv_bfloat162*)&Clo[(size_t)r1 * N + c] = lp;
            }
        }
    }
}

__global__ void __launch_bounds__(256)
bgemm_pre_kernel(const __nv_bfloat16* __restrict__ Ahi, const __nv_bfloat16* __restrict__ Alo,
                 const __nv_bfloat16* __restrict__ Bhi, const __nv_bfloat16* __restrict__ Blo,
                 const float* __restrict__ bias, const float* __restrict__ resid,
                 float* __restrict__ C, __nv_bfloat16* __restrict__ Chi,
                 __nv_bfloat16* __restrict__ Clo, int N, int K) {
    bgemm_pre_body(Ahi, Alo, Bhi, Blo, bias, resid, C, Chi, Clo,
                   N, K, blockIdx.y * 128, blockIdx.x * 64);
}

// ---------------------------------------------------------------------------
// GRU recurrent GEMM, 64M x 64N tiles: gh[d] = hcur[d] @ Whh_d^T
// grid (12 nt, 4 mt, 2 dir), 128 threads (4 warps = 2m x 2n of 32x32).
// ---------------------------------------------------------------------------
__global__ void __launch_bounds__(128)
gru_gh_kernel() {
    extern __shared__ __align__(16) char dynsm[];
    __nv_bfloat16 (*As)[2][64][BKP] =
        reinterpret_cast<__nv_bfloat16 (*)[2][64][BKP]>(dynsm);
    __nv_bfloat16 (*Bs)[2][64][BKP] =
        reinterpret_cast<__nv_bfloat16 (*)[2][64][BKP]>(dynsm + SMEM_A64);

    int nt = blockIdx.x, mt = blockIdx.y, d = blockIdx.z;
    int tid = threadIdx.x;
    int warp = tid >> 5, lane = tid & 31;
    int wm = (warp & 1) * 32;
    int wn = (warp >> 1) * 32;
    int m0 = mt * 64, n0 = nt * 64;

    const __nv_bfloat16* Ahi = g_hcur_s[0] + (size_t)d * NB * HD;
    const __nv_bfloat16* Alo = g_hcur_s[1] + (size_t)d * NB * HD;
    size_t woff = WOFF_GRU + (d ? 3 : 1) * (size_t)WGRU;
    const __nv_bfloat16* Bhi = g_w_s[0] + woff;
    const __nv_bfloat16* Blo = g_w_s[1] + woff;

    float acc[2][4][4];
#pragma unroll
    for (int i = 0; i < 2; i++)
#pragma unroll
        for (int j = 0; j < 4; j++)
#pragma unroll
            for (int r = 0; r < 4; r++) acc[i][j][r] = 0.f;

    auto load_stage = [&](int s, int k0) {
#pragma unroll
        for (int l = 0; l < 4; l++) {               // A: 512 uint4 / 128 thr
            int idx = tid + l * 128;
            int plane = idx >> 8, r = idx & 255;
            int row = r >> 2, c16 = r & 3;
            const __nv_bfloat16* src = (plane ? Alo : Ahi) +
                (size_t)(m0 + row) * HD + k0 + c16 * 8;
            cpa16(s2u(&As[s][plane][row][c16 * 8]), src);
        }
#pragma unroll
        for (int l = 0; l < 4; l++) {               // B: 512 uint4 / 128 thr
            int idx = tid + l * 128;
            int plane = idx >> 8, r = idx & 255;
            int row = r >> 2, c16 = r & 3;
            const __nv_bfloat16* src = (plane ? Blo : Bhi) +
                (size_t)(n0 + row) * HD + k0 + c16 * 8;
            cpa16(s2u(&Bs[s][plane][row][c16 * 8]), src);
        }
    };

    const int KT = HD / 32;
    load_stage(0, 0);
    CP_COMMIT();

    for (int kt = 0; kt < KT; kt++) {
        if (kt + 1 < KT) {
            load_stage((kt + 1) & 1, (kt + 1) * 32);
            CP_COMMIT();
            CP_WAIT1();
        } else {
            CP_WAIT0();
        }
        __syncthreads();

        int s = kt & 1;
        int r = lane & 15, cg = lane >> 4;
#pragma unroll
        for (int kk = 0; kk < 32; kk += 16) {
            unsigned ah[2][4], al[2][4];
#pragma unroll
            for (int mf = 0; mf < 2; mf++) {
                ldmx4(s2u(&As[s][0][wm + mf*16 + r][kk + cg*8]),
                      ah[mf][0], ah[mf][1], ah[mf][2], ah[mf][3]);
                ldmx4(s2u(&As[s][1][wm + mf*16 + r][kk + cg*8]),
                      al[mf][0], al[mf][1], al[mf][2], al[mf][3]);
            }
            unsigned bh[4][2], bl[4][2];
#pragma unroll
            for (int bf = 0; bf < 2; bf++) {
                unsigned q0, q1, q2, q3;
                ldmx4(s2u(&Bs[s][0][wn + bf*16 + r][kk + cg*8]), q0, q1, q2, q3);
                bh[bf*2+0][0] = q0; bh[bf*2+1][0] = q1;
                bh[bf*2+0][1] = q2; bh[bf*2+1][1] = q3;
                ldmx4(s2u(&Bs[s][1][wn + bf*16 + r][kk + cg*8]), q0, q1, q2, q3);
                bl[bf*2+0][0] = q0; bl[bf*2+1][0] = q1;
                bl[bf*2+0][1] = q2; bl[bf*2+1][1] = q3;
            }
#pragma unroll
            for (int mf = 0; mf < 2; mf++)
#pragma unroll
                for (int nf = 0; nf < 4; nf++) {
                    mma_bf16(acc[mf][nf], ah[mf][0], ah[mf][1], ah[mf][2], ah[mf][3],
                             bh[nf][0], bh[nf][1]);
                    mma_bf16(acc[mf][nf], ah[mf][0], ah[mf][1], ah[mf][2], ah[mf][3],
                             bl[nf][0], bl[nf][1]);
                    mma_bf16(acc[mf][nf], al[mf][0], al[mf][1], al[mf][2], al[mf][3],
                             bh[nf][0], bh[nf][1]);
                }
        }
        __syncthreads();
    }

    float* ghbase = g_gh + (size_t)d * NB * G3;
    int g = lane >> 2, tg = lane & 3;
#pragma unroll
    for (int mf = 0; mf < 2; mf++) {
#pragma unroll
        for (int nf = 0; nf < 4; nf++) {
            int c = n0 + wn + nf * 8 + tg * 2;
            int r0 = m0 + wm + mf * 16 + g;
            int r1 = r0 + 8;
            float2 oa; oa.x = acc[mf][nf][0]; oa.y = acc[mf][nf][1];
            float2 ob; ob.x = acc[mf][nf][2]; ob.y = acc[mf][nf][3];
            *(float2*)&ghbase[(size_t)r0 * G3 + c] = oa;
            *(float2*)&ghbase[(size_t)r1 * G3 + c] = ob;
        }
    }
}

// -------------------------- attention (fp32 in, split out) -------------------
template <int LQ, int LK>
__global__ void attn_kernel(const float* __restrict__ qh,
                            const float* __restrict__ kh,
                            const float* __restrict__ vh,
                            const int* __restrict__ qc,
                            const int* __restrict__ kc,
                            __nv_bfloat16* __restrict__ ohi,
                            __nv_bfloat16* __restrict__ olo) {
    __shared__ float ks[LK * DKH];
    __shared__ float vs[LK * DKH];
    int bh = blockIdx.x;
    int b = bh / NHEAD, hd = bh % NHEAD;
    for (int idx = threadIdx.x; idx < LK * DKH; idx += blockDim.x) {
        int k = idx / DKH, i = idx % DKH;
        size_t base = ((size_t)(b * LK) + k) * HD + hd * DKH + i;
        ks[idx] = kh[base];
        vs[idx] = vh[base];
    }
    __syncthreads();
    int q = threadIdx.x;
    if (q >= LQ) return;

    float qreg[DKH];
    const float* qp = &qh[((size_t)(b * LQ) + q) * HD + hd * DKH];
#pragma unroll
    for (int i = 0; i < DKH; i++) qreg[i] = qp[i];

    bool vq = q < qc[b];
    int kcnt = kc[b];
    float s[LK];
    float mx = -3.402823e38f;
#pragma unroll
    for (int k = 0; k < LK; k++) {
        float dd = 0.f;
#pragma unroll
        for (int i = 0; i < DKH; i++) dd = fmaf(qreg[i], ks[k * DKH + i], dd);
        float val = (vq && k < kcnt) ? dd * 0.125f : -1e9f;
        s[k] = val;
        mx = fmaxf(mx, val);
    }
    float sum = 0.f;
#pragma unroll
    for (int k = 0; k < LK; k++) { s[k] = expf(s[k] - mx); sum += s[k]; }
    float inv = 1.f / sum;
    size_t obase = ((size_t)(b * LQ) + q) * HD + hd * DKH;
#pragma unroll
    for (int i = 0; i < DKH; i++) {
        float a = 0.f;
#pragma unroll
        for (int k = 0; k < LK; k++) a = fmaf(s[k], vs[k * DKH + i], a);
        a *= inv;
        __nv_bfloat16 h, l;
        split_bf16(a, h, l);
        ohi[obase + i] = h;
        olo[obase + i] = l;
    }
}

// -------------------------- h0 = max over t (+ split) ------------------------
__global__ void hmax_kernel() {
    int b = blockIdx.x, j = threadIdx.x;
    float m = -3.402823e38f;
    for (int t = 0; t < TNA; t++)
        m = fmaxf(m, g_h[((size_t)(b * TNA) + t) * HD + j]);
    size_t i0 = (size_t)b * HD + j;
    size_t i1 = (size_t)NB * HD + i0;
    g_hcur[i0] = m; g_hcur[i1] = m;
    __nv_bfloat16 h, l;
    split_bf16(m, h, l);
    g_hcur_s[0][i0] = h; g_hcur_s[0][i1] = h;
    g_hcur_s[1][i0] = l; g_hcur_s[1][i1] = l;
}

__global__ void zero_outsum_kernel() {
    int idx = blockIdx.x * blockDim.x + threadIdx.x;
    g_outsum[idx] = 0.f;
}

// -------------------------- GRU gate update, float4 / thread -----------------
__global__ void __launch_bounds__(256)
gru_gate_kernel(const float* __restrict__ bhh_f, const float* __restrict__ bhh_b,
                const int* __restrict__ counts, int t) {
    int idx = blockIdx.x * 256 + threadIdx.x;   // 0 .. 32767
    int d = idx >> 14;
    int b = (idx >> 6) & 255;
    int j = (idx & 63) * 4;
    int teff = d ? (TNA - 1 - t) : t;
    const float* gi = (d ? g_gi_b : g_gi_f) + ((size_t)(b * TNA) + teff) * G3;
    const float* bhh = d ? bhh_b : bhh_f;
    const float* gh = g_gh + (size_t)d * NB * G3 + (size_t)b * G3;

    float4 gir = *(const float4*)&gi[j];
    float4 giz = *(const float4*)&gi[j + 256];
    float4 gin = *(const float4*)&gi[j + 512];
    float4 ghr = *(const float4*)&gh[j];
    float4 ghz = *(const float4*)&gh[j + 256];
    float4 ghn = *(const float4*)&gh[j + 512];
    float4 bhr = *(const float4*)&bhh[j];
    float4 bhz = *(const float4*)&bhh[j + 256];
    float4 bhn = *(const float4*)&bhh[j + 512];

    size_t hidx = (size_t)d * NB * HD + (size_t)b * HD + j;
    float4 hp = *(float4*)&g_hcur[hidx];

    float irv[4] = {gir.x, gir.y, gir.z, gir.w};
    float izv[4] = {giz.x, giz.y, giz.z, giz.w};
    float inv_[4] = {gin.x, gin.y, gin.z, gin.w};
    float grv[4] = {ghr.x, ghr.y, ghr.z, ghr.w};
    float gzv[4] = {ghz.x, ghz.y, ghz.z, ghz.w};
    float gnv[4] = {ghn.x, ghn.y, ghn.z, ghn.w};
    float brv[4] = {bhr.x, bhr.y, bhr.z, bhr.w};
    float bzv[4] = {bhz.x, bhz.y, bhz.z, bhz.w};
    float bnv[4] = {bhn.x, bhn.y, bhn.z, bhn.w};
    float hpv[4] = {hp.x, hp.y, hp.z, hp.w};
    float hv[4];
#pragma unroll
    for (int c = 0; c < 4; c++) {
        float r = 1.f / (1.f + expf(-(irv[c] + grv[c] + brv[c])));
        float z = 1.f / (1.f + expf(-(izv[c] + gzv[c] + bzv[c])));
        float n = tanhf(inv_[c] + r * (gnv[c] + bnv[c]));
        hv[c] = (1.f - z) * n + z * hpv[c];
    }
    float4 ho; ho.x = hv[0]; ho.y = hv[1]; ho.z = hv[2]; ho.w = hv[3];
    *(float4*)&g_hcur[hidx] = ho;

    __nv_bfloat16 h0,l0,h1,l1,h2,l2,h3,l3;
    split_bf16(hv[0], h0, l0); split_bf16(hv[1], h1, l1);
    split_bf16(hv[2], h2, l2); split_bf16(hv[3], h3, l3);
    __nv_bfloat162 ha; ha.x = h0; ha.y = h1;
    __nv_bfloat162 hb; hb.x = h2; hb.y = h3;
    __nv_bfloat162 la; la.x = l0; la.y = l1;
    __nv_bfloat162 lb; lb.x = l2; lb.y = l3;
    ((__nv_bfloat162*)&g_hcur_s[0][hidx])[0] = ha;
    ((__nv_bfloat162*)&g_hcur_s[0][hidx])[1] = hb;
    ((__nv_bfloat162*)&g_hcur_s[1][hidx])[0] = la;
    ((__nv_bfloat162*)&g_hcur_s[1][hidx])[1] = lb;

    if (teff < counts[b]) {
        float4 os = *(float4*)&g_outsum[hidx];
        os.x += hv[0]; os.y += hv[1]; os.z += hv[2]; os.w += hv[3];
        *(float4*)&g_outsum[hidx] = os;
    }
}

__global__ void final_kernel(const int* __restrict__ counts, float* __restrict__ out) {
    int idx = blockIdx.x * blockDim.x + threadIdx.x;
    int d = idx >> 16;
    int b = (idx >> 8) & 255;
    int j = idx & 255;
    float c = (float)counts[b];
    out[(size_t)b * 512 + d * 256 + j] =
        g_outsum[(size_t)d * NB * HD + (size_t)b * HD + j] / c;
}

// -------------------------- host launch -------------------------------------
template <typename T>
static T* symaddr(const void* sym) {
    void* p = nullptr;
    cudaGetSymbolAddress(&p, sym);
    return (T*)p;
}

extern "C" void kernel_launch(void* const* d_in, const int* in_sizes, int n_in,
                              void* d_out, int out_size) {
    int wbase, ci0, ci1, ci2;
    if (in_sizes[3] == NB) { ci0 = 3; ci1 = 4; ci2 = 5; wbase = 6; }
    else { wbase = 3; ci0 = n_in - 3; ci1 = n_in - 2; ci2 = n_in - 1; }

    const float* atom_msg  = (const float*)d_in[0];
    const float* pharm_msg = (const float*)d_in[1];
    const float* hyper_msg = (const float*)d_in[2];
    const int* ac = (const int*)d_in[ci0];
    const int* pc = (const int*)d_in[ci1];
    const int* hc = (const int*)d_in[ci2];

    const float* p2h[8];
    const float* a2p[8];
    for (int i = 0; i < 8; i++) p2h[i] = (const float*)d_in[wbase + i];
    for (int i = 0; i < 8; i++) a2p[i] = (const float*)d_in[wbase + 8 + i];
    const float* Wih_f = (const float*)d_in[wbase + 16];
    const float* Whh_f = (const float*)d_in[wbase + 17];
    const float* bih_f = (const float*)d_in[wbase + 18];
    const float* bhh_f = (const float*)d_in[wbase + 19];
    const float* Wih_b = (const float*)d_in[wbase + 20];
    const float* Whh_b = (const float*)d_in[wbase + 21];
    const float* bih_b = (const float*)d_in[wbase + 22];
    const float* bhh_b = (const float*)d_in[wbase + 23];

    float* atom_f  = symaddr<float>(g_atom_f);
    float* pharm_f = symaddr<float>(g_pharm_f);
    float* hyper_f = symaddr<float>(g_hyper_f);
    float* q1 = symaddr<float>(g_q1);
    float* k1 = symaddr<float>(g_k1);
    float* v1 = symaddr<float>(g_v1);
    float* q2 = symaddr<float>(g_q2);
    float* k2 = symaddr<float>(g_k2);
    float* v2 = symaddr<float>(g_v2);
    float* pharm2 = symaddr<float>(g_pharm2);
    float* hbuf = symaddr<float>(g_h);
    float* gi_f = symaddr<float>(g_gi_f);
    float* gi_b = symaddr<float>(g_gi_b);

    __nv_bfloat16* atom_s  = symaddr<__nv_bfloat16>(g_atom_s);
    __nv_bfloat16* pharm_s = symaddr<__nv_bfloat16>(g_pharm_s);
    __nv_bfloat16* hyper_s = symaddr<__nv_bfloat16>(g_hyper_s);
    __nv_bfloat16* o1_s    = symaddr<__nv_bfloat16>(g_o1_s);
    __nv_bfloat16* pharm2_s= symaddr<__nv_bfloat16>(g_pharm2_s);
    __nv_bfloat16* o2_s    = symaddr<__nv_bfloat16>(g_o2_s);
    __nv_bfloat16* h_s     = symaddr<__nv_bfloat16>(g_h_s);
    __nv_bfloat16* w_s     = symaddr<__nv_bfloat16>(g_w_s);

    const size_t SA = (size_t)NB*TNA*HD;
    const size_t SP = (size_t)NB*TNP*HD;
    const size_t SH = (size_t)NB*TNH*HD;
    __nv_bfloat16 *atom_hi = atom_s,   *atom_lo = atom_s + SA;
    __nv_bfloat16 *pharm_hi = pharm_s, *pharm_lo = pharm_s + SP;
    __nv_bfloat16 *hyper_hi = hyper_s, *hyper_lo = hyper_s + SH;
    __nv_bfloat16 *o1_hi = o1_s,       *o1_lo = o1_s + SP;
    __nv_bfloat16 *pharm2_hi = pharm2_s, *pharm2_lo = pharm2_s + SP;
    __nv_bfloat16 *o2_hi = o2_s,       *o2_lo = o2_s + SA;
    __nv_bfloat16 *h_hi = h_s,         *h_lo = h_s + SA;
    __nv_bfloat16 *w_hi = w_s,         *w_lo = w_s + WTOT;

    float* out = (float*)d_out;

    const int MA = NB * TNA;   // 32512 = 254*128
    const int MP = NB * TNP;   // 5888  = 46*128
    const int MH = NB * TNH;   // 2816  = 22*128

    cudaFuncSetAttribute(bgemm_pre_kernel,
                         cudaFuncAttributeMaxDynamicSharedMemorySize, GEMM_SMEM);
    cudaFuncSetAttribute(gru_gh_kernel,
                         cudaFuncAttributeMaxDynamicSharedMemorySize, GRU_SMEM);

    prefix_kernel<<<1, 32>>>(ac, pc, hc);

    // ---- pre-split all 12 weight matrices in one batched launch ----
    WSrcs ws;
    ws.p[0] = p2h[0]; ws.p[1] = p2h[2]; ws.p[2] = p2h[4]; ws.p[3] = p2h[6];
    ws.p[4] = a2p[0]; ws.p[5] = a2p[2]; ws.p[6] = a2p[4]; ws.p[7] = a2p[6];
    ws.p[8] = Wih_f;  ws.p[9] = Whh_f;  ws.p[10] = Wih_b; ws.p[11] = Whh_b;
    wsplit_all_kernel<<<2048 + 4 * 768, 256>>>(ws, w_hi, w_lo);

    // ---- gathers (+split) ----
    gather_kernel<<<dim3(TNA, NB), 64>>>(atom_msg,  ac, 0, atom_f,  atom_hi,  atom_lo,  TNA);
    gather_kernel<<<dim3(TNP, NB), 64>>>(pharm_msg, pc, 1, pharm_f, pharm_hi, pharm_lo, TNP);
    gather_kernel<<<dim3(TNH, NB), 64>>>(hyper_msg, hc, 2, hyper_f, hyper_hi, hyper_lo, TNH);

    // ---- MHA1 ----
    bgemm_pre_kernel<<<dim3(HD/64, MP/128), 256, GEMM_SMEM>>>(pharm_hi, pharm_lo,
        w_hi + 0*WPROJ, w_lo + 0*WPROJ, p2h[1], nullptr, q1, nullptr, nullptr, HD, HD);
    bgemm_pre_kernel<<<dim3(HD/64, MH/128), 256, GEMM_SMEM>>>(hyper_hi, hyper_lo,
        w_hi + 1*WPROJ, w_lo + 1*WPROJ, p2h[3], nullptr, k1, nullptr, nullptr, HD, HD);
    bgemm_pre_kernel<<<dim3(HD/64, MH/128), 256, GEMM_SMEM>>>(hyper_hi, hyper_lo,
        w_hi + 2*WPROJ, w_lo + 2*WPROJ, p2h[5], nullptr, v1, nullptr, nullptr, HD, HD);
    attn_kernel<TNP, TNH><<<NB * NHEAD, 32>>>(q1, k1, v1, pc, hc, o1_hi, o1_lo);
    bgemm_pre_kernel<<<dim3(HD/64, MP/128), 256, GEMM_SMEM>>>(o1_hi, o1_lo,
        w_hi + 3*WPROJ, w_lo + 3*WPROJ, p2h[7], pharm_f, pharm2, pharm2_hi, pharm2_lo, HD, HD);

    // ---- MHA2 ----
    bgemm_pre_kernel<<<dim3(HD/64, MA/128), 256, GEMM_SMEM>>>(atom_hi, atom_lo,
        w_hi + 4*WPROJ, w_lo + 4*WPROJ, a2p[1], nullptr, q2, nullptr, nullptr, HD, HD);
    bgemm_pre_kernel<<<dim3(HD/64, MP/128), 256, GEMM_SMEM>>>(pharm2_hi, pharm2_lo,
        w_hi + 5*WPROJ, w_lo + 5*WPROJ, a2p[3], nullptr, k2, nullptr, nullptr, HD, HD);
    bgemm_pre_kernel<<<dim3(HD/64, MP/128), 256, GEMM_SMEM>>>(pharm2_hi, pharm2_lo,
        w_hi + 6*WPROJ, w_lo + 6*WPROJ, a2p[5], nullptr, v2, nullptr, nullptr, HD, HD);
    attn_kernel<TNA, TNP><<<NB * NHEAD, 128>>>(q2, k2, v2, ac, pc, o2_hi, o2_lo);
    bgemm_pre_kernel<<<dim3(HD/64, MA/128), 256, GEMM_SMEM>>>(o2_hi, o2_lo,
        w_hi + 7*WPROJ, w_lo + 7*WPROJ, a2p[7], atom_f, hbuf, h_hi, h_lo, HD, HD);

    // ---- h0 = max over t ----
    hmax_kernel<<<NB, HD>>>();

    // ---- gi = h @ Wih^T + bih ----
    bgemm_pre_kernel<<<dim3(G3/64, MA/128), 256, GEMM_SMEM>>>(h_hi, h_lo,
        w_hi + WOFF_GRU + 0*WGRU, w_lo + WOFF_GRU + 0*WGRU, bih_f, nullptr,
        gi_f, nullptr, nullptr, G3, HD);
    bgemm_pre_kernel<<<dim3(G3/64, MA/128), 256, GEMM_SMEM>>>(h_hi, h_lo,
        w_hi + WOFF_GRU + 2*WGRU, w_lo + WOFF_GRU + 2*WGRU, bih_b, nullptr,
        gi_b, nullptr, nullptr, G3, HD);

    // ---- GRU recurrence: per-step GEMM (96 blocks) + vectorized gate ----
    zero_outsum_kernel<<<(2 * NB * HD) / 256, 256>>>();
    for (int t = 0; t < TNA; t++) {
        gru_gh_kernel<<<dim3(G3/64, 4, 2), 128, GRU_SMEM>>>();
        gru_gate_kernel<<<(2 * NB * HD / 4) / 256, 256>>>(bhh_f, bhh_b, ac, t);
    }

    final_kernel<<<(2 * NB * HD) / 256, 256>>>(ac, out);
    (void)out_size; (void)n_in;
}